// round 1
// baseline (speedup 1.0000x reference)
#include <cuda_runtime.h>
#include <cuda_bf16.h>
#include <cstdint>
#include <math.h>

#define NTOK 4096
#define DDIM 768
#define HDIM 1536
#define NE   6

// ---------------- device scratch (no allocations allowed) ----------------
__device__ int   g_perm[NTOK];
__device__ int   g_gstart[NE + 1];
__device__ float g_alpha[NE];
__device__ __nv_bfloat16 g_xg[(size_t)NTOK * DDIM];          // gathered x, perm order
__device__ __nv_bfloat16 g_h [(size_t)NTOK * HDIM];          // relu hidden, perm order
__device__ __nv_bfloat16 g_W1t[(size_t)NE * HDIM * DDIM];    // [e][h][d]  (N-major, K contiguous)
__device__ __nv_bfloat16 g_W2t[(size_t)NE * DDIM * HDIM];    // [e][d][h]
__device__ float g_pre[(size_t)NTOK * DDIM];                 // x + alpha*r, token order

// ---------------- prep: sort tokens by group ----------------
__global__ void prep_kernel(const int* __restrict__ ids,
                            const int* __restrict__ e2g,
                            const float* __restrict__ raw_alpha,
                            int T) {
    __shared__ int cnt[NE];
    __shared__ int cur[NE];
    __shared__ unsigned char gid_s[NTOK];
    int tid = threadIdx.x;
    if (tid < NE) cnt[tid] = 0;
    __syncthreads();
    for (int i = tid; i < NTOK; i += blockDim.x) {
        int ty = ids[i];
        ty = ty < 0 ? 0 : (ty > T - 1 ? T - 1 : ty);
        int gd = e2g[ty];
        gid_s[i] = (unsigned char)gd;
        atomicAdd(&cnt[gd], 1);
    }
    __syncthreads();
    if (tid == 0) {
        int acc = 0;
        for (int e = 0; e < NE; e++) { g_gstart[e] = acc; cur[e] = acc; acc += cnt[e]; }
        g_gstart[NE] = acc;
    }
    __syncthreads();
    for (int i = tid; i < NTOK; i += blockDim.x) {
        int pos = atomicAdd(&cur[gid_s[i]], 1);
        g_perm[pos] = i;
    }
    if (tid < NE) g_alpha[tid] = 0.05f / (1.0f + expf(-raw_alpha[tid]));
}

// ---------------- weight transpose + fp32->bf16 convert ----------------
// in: [E][R][C] fp32  ->  out: [E][C][R] bf16.  which: 0 -> g_W1t, 1 -> g_W2t
__global__ void transpose_kernel(const float* __restrict__ in, int R, int C, int which) {
    __shared__ float tile[32][33];
    __nv_bfloat16* out = which ? g_W2t : g_W1t;
    int e  = blockIdx.z;
    int c0 = blockIdx.x * 32, r0 = blockIdx.y * 32;
    const float* inp = in + (size_t)e * R * C;
    __nv_bfloat16* op = out + (size_t)e * R * C;
    int tx = threadIdx.x, ty = threadIdx.y;
    #pragma unroll
    for (int j = ty; j < 32; j += 8)
        tile[j][tx] = inp[(size_t)(r0 + j) * C + c0 + tx];
    __syncthreads();
    #pragma unroll
    for (int j = ty; j < 32; j += 8)
        op[(size_t)(c0 + j) * R + r0 + tx] = __float2bfloat16(tile[tx][j]);
}

// ---------------- gather x rows in perm order, fp32 -> bf16 ----------------
__global__ void gather_kernel(const float* __restrict__ x) {
    int p = blockIdx.x;
    int t = g_perm[p];
    const float* xr = x + (size_t)t * DDIM;
    __nv_bfloat16* o = g_xg + (size_t)p * DDIM;
    for (int d = threadIdx.x; d < DDIM; d += blockDim.x)
        o[d] = __float2bfloat16(xr[d]);
}

// ---------------- bf16 warp MMA helper ----------------
__device__ __forceinline__ void mma16816(float* c, const uint32_t* a, const uint32_t* b) {
    asm volatile(
        "mma.sync.aligned.m16n8k16.row.col.f32.bf16.bf16.f32 "
        "{%0,%1,%2,%3}, {%4,%5,%6,%7}, {%8,%9}, {%0,%1,%2,%3};\n"
        : "+f"(c[0]), "+f"(c[1]), "+f"(c[2]), "+f"(c[3])
        : "r"(a[0]), "r"(a[1]), "r"(a[2]), "r"(a[3]), "r"(b[0]), "r"(b[1]));
}

// ---------------- grouped GEMM ----------------
// EPI2 == false : g_h[p,:] = relu(g_xg[p,:] @ W1[g] + b1[g])   (bf16 out)
// EPI2 == true  : g_pre[t,:] = x[t,:] + alpha[g] * (g_h[p,:] @ W2[g] + b2[g])
template<int K, bool EPI2>
__global__ void __launch_bounds__(256) gemm_kernel(
    const float* __restrict__ bias,   // [E][Ntot] fp32
    const float* __restrict__ x)      // used only when EPI2
{
    constexpr int BM = 128, BN = 128, BK = 32, PAD = 8;
    constexpr int NTOT = EPI2 ? DDIM : HDIM;
    __shared__ __align__(16) __nv_bfloat16 As[BM][BK + PAD];
    __shared__ __align__(16) __nv_bfloat16 Bs[BN][BK + PAD];

    const __nv_bfloat16* A  = EPI2 ? g_h   : g_xg;
    const __nv_bfloat16* Bt = EPI2 ? g_W2t : g_W1t;

    int g     = blockIdx.z;
    int start = g_gstart[g];
    int cnt   = g_gstart[g + 1] - start;
    int m0    = blockIdx.x * BM;
    if (m0 >= cnt) return;
    int n0 = blockIdx.y * BN;
    const __nv_bfloat16* Bg = Bt + (size_t)g * NTOT * K;

    int tid  = threadIdx.x;
    int warp = tid >> 5, lane = tid & 31;
    int wm = (warp & 3) * 32;   // warp M offset within CTA tile
    int wn = (warp >> 2) * 64;  // warp N offset

    float acc[2][8][4];
    #pragma unroll
    for (int mi = 0; mi < 2; mi++)
        #pragma unroll
        for (int ni = 0; ni < 8; ni++)
            #pragma unroll
            for (int q = 0; q < 4; q++) acc[mi][ni][q] = 0.f;

    int lrow = lane >> 2;        // 0..7
    int lcol = (lane & 3) * 2;   // 0,2,4,6

    for (int k0 = 0; k0 < K; k0 += BK) {
        // ---- load A tile (row-guarded, zero fill) ----
        #pragma unroll
        for (int s = tid; s < BM * 4; s += 256) {
            int r = s >> 2, v = s & 3;
            uint4 d = make_uint4(0u, 0u, 0u, 0u);
            if (m0 + r < cnt)
                d = *reinterpret_cast<const uint4*>(
                        A + (size_t)(start + m0 + r) * K + k0 + v * 8);
            *reinterpret_cast<uint4*>(&As[r][v * 8]) = d;
        }
        // ---- load B tile ----
        #pragma unroll
        for (int s = tid; s < BN * 4; s += 256) {
            int r = s >> 2, v = s & 3;
            uint4 d = *reinterpret_cast<const uint4*>(
                        Bg + (size_t)(n0 + r) * K + k0 + v * 8);
            *reinterpret_cast<uint4*>(&Bs[r][v * 8]) = d;
        }
        __syncthreads();

        #pragma unroll
        for (int kk = 0; kk < BK; kk += 16) {
            uint32_t af[2][4], bfr[8][2];
            #pragma unroll
            for (int mi = 0; mi < 2; mi++) {
                int r = wm + mi * 16;
                af[mi][0] = *reinterpret_cast<const uint32_t*>(&As[r + lrow    ][kk + lcol    ]);
                af[mi][1] = *reinterpret_cast<const uint32_t*>(&As[r + lrow + 8][kk + lcol    ]);
                af[mi][2] = *reinterpret_cast<const uint32_t*>(&As[r + lrow    ][kk + lcol + 8]);
                af[mi][3] = *reinterpret_cast<const uint32_t*>(&As[r + lrow + 8][kk + lcol + 8]);
            }
            #pragma unroll
            for (int ni = 0; ni < 8; ni++) {
                int c = wn + ni * 8 + lrow;
                bfr[ni][0] = *reinterpret_cast<const uint32_t*>(&Bs[c][kk + lcol    ]);
                bfr[ni][1] = *reinterpret_cast<const uint32_t*>(&Bs[c][kk + lcol + 8]);
            }
            #pragma unroll
            for (int mi = 0; mi < 2; mi++)
                #pragma unroll
                for (int ni = 0; ni < 8; ni++)
                    mma16816(acc[mi][ni], af[mi], bfr[ni]);
        }
        __syncthreads();
    }

    // ---- epilogue ----
    float alpha = EPI2 ? g_alpha[g] : 0.f;
    const float* bg = bias + (size_t)g * NTOT;
    #pragma unroll
    for (int mi = 0; mi < 2; mi++) {
        #pragma unroll
        for (int half = 0; half < 2; half++) {
            int rloc = wm + mi * 16 + lrow + half * 8;
            int grow = m0 + rloc;
            if (grow >= cnt) continue;
            #pragma unroll
            for (int ni = 0; ni < 8; ni++) {
                int c = n0 + wn + ni * 8 + lcol;
                float v0 = acc[mi][ni][half * 2 + 0] + bg[c];
                float v1 = acc[mi][ni][half * 2 + 1] + bg[c + 1];
                if (!EPI2) {
                    v0 = fmaxf(v0, 0.f);
                    v1 = fmaxf(v1, 0.f);
                    __nv_bfloat162 pk = __floats2bfloat162_rn(v0, v1);
                    *reinterpret_cast<__nv_bfloat162*>(
                        &g_h[(size_t)(start + grow) * HDIM + c]) = pk;
                } else {
                    int t = g_perm[start + grow];
                    float2 xv = *reinterpret_cast<const float2*>(x + (size_t)t * DDIM + c);
                    float2 o;
                    o.x = xv.x + alpha * v0;
                    o.y = xv.y + alpha * v1;
                    *reinterpret_cast<float2*>(&g_pre[(size_t)t * DDIM + c]) = o;
                }
            }
        }
    }
}

// ---------------- normalize: out = pre / max(||pre||, 1e-12) ----------------
__global__ void normalize_kernel(float* __restrict__ out) {
    int t = blockIdx.x;
    const float* pr = g_pre + (size_t)t * DDIM;
    float v[3];
    float s = 0.f;
    #pragma unroll
    for (int i = 0; i < 3; i++) {
        v[i] = pr[threadIdx.x + i * 256];
        s += v[i] * v[i];
    }
    #pragma unroll
    for (int o = 16; o > 0; o >>= 1) s += __shfl_xor_sync(0xffffffffu, s, o);
    __shared__ float red[8];
    int warp = threadIdx.x >> 5, lane = threadIdx.x & 31;
    if (lane == 0) red[warp] = s;
    __syncthreads();
    if (warp == 0) {
        float z = (lane < 8) ? red[lane] : 0.f;
        #pragma unroll
        for (int o = 4; o > 0; o >>= 1) z += __shfl_xor_sync(0xffffffffu, z, o);
        if (lane == 0) red[0] = z;
    }
    __syncthreads();
    float inv = 1.f / fmaxf(sqrtf(red[0]), 1e-12f);
    float* op = out + (size_t)t * DDIM;
    #pragma unroll
    for (int i = 0; i < 3; i++) op[threadIdx.x + i * 256] = v[i] * inv;
}

// ---------------- launch ----------------
extern "C" void kernel_launch(void* const* d_in, const int* in_sizes, int n_in,
                              void* d_out, int out_size) {
    const float* x         = (const float*)d_in[0];
    const int*   ids       = (const int*)d_in[1];
    const float* W1        = (const float*)d_in[2];
    const float* b1        = (const float*)d_in[3];
    const float* W2        = (const float*)d_in[4];
    const float* b2        = (const float*)d_in[5];
    const float* raw_alpha = (const float*)d_in[6];
    const int*   e2g       = (const int*)d_in[7];
    int T = in_sizes[7];

    prep_kernel<<<1, 256>>>(ids, e2g, raw_alpha, T);

    // W1 [E][D][H] -> g_W1t [E][H][D] ;  W2 [E][H][D] -> g_W2t [E][D][H]
    transpose_kernel<<<dim3(HDIM / 32, DDIM / 32, NE), dim3(32, 8)>>>(W1, DDIM, HDIM, 0);
    transpose_kernel<<<dim3(DDIM / 32, HDIM / 32, NE), dim3(32, 8)>>>(W2, HDIM, DDIM, 1);

    gather_kernel<<<NTOK, 256>>>(x);

    // GEMM1: [cnt_g, 768] x [768, 1536] + b1 -> relu -> g_h
    gemm_kernel<DDIM, false><<<dim3(NTOK / 128, HDIM / 128, NE), 256>>>(b1, nullptr);
    // GEMM2: [cnt_g, 1536] x [1536, 768] + b2 -> x + alpha*r -> g_pre (token order)
    gemm_kernel<HDIM, true ><<<dim3(NTOK / 128, DDIM / 128, NE), 256>>>(b2, x);

    normalize_kernel<<<NTOK, 256>>>((float*)d_out);
}

// round 2
// speedup vs baseline: 1.1135x; 1.1135x over previous
#include <cuda_runtime.h>
#include <cuda_bf16.h>
#include <cstdint>
#include <math.h>

#define NTOK 4096
#define DDIM 768
#define HDIM 1536
#define NE   6

// ---------------- device scratch (no allocations allowed) ----------------
__device__ int   g_perm[NTOK];
__device__ int   g_gstart[NE + 1];
__device__ float g_alpha[NE];
__device__ __nv_bfloat16 g_h [(size_t)NTOK * HDIM];          // relu hidden, perm order
__device__ __nv_bfloat16 g_W1t[(size_t)NE * HDIM * DDIM];    // [e][h][d]  (N-major, K contiguous)
__device__ __nv_bfloat16 g_W2t[(size_t)NE * DDIM * HDIM];    // [e][d][h]
__device__ float g_pre[(size_t)NTOK * DDIM];                 // x + alpha*r, token order

// ---------------- cp.async helpers ----------------
__device__ __forceinline__ void cp_async16(void* smem, const void* g, bool pred) {
    uint32_t s = (uint32_t)__cvta_generic_to_shared(smem);
    int sz = pred ? 16 : 0;
    asm volatile("cp.async.cg.shared.global [%0], [%1], 16, %2;\n" :: "r"(s), "l"(g), "r"(sz));
}
#define CP_COMMIT() asm volatile("cp.async.commit_group;\n" ::: "memory")
#define CP_WAIT0()  asm volatile("cp.async.wait_group 0;\n" ::: "memory")

// ---------------- prep: sort tokens by group ----------------
__global__ void prep_kernel(const int* __restrict__ ids,
                            const int* __restrict__ e2g,
                            const float* __restrict__ raw_alpha,
                            int T) {
    __shared__ int cnt[NE];
    __shared__ int cur[NE];
    __shared__ unsigned char gid_s[NTOK];
    int tid = threadIdx.x;
    if (tid < NE) cnt[tid] = 0;
    __syncthreads();
    for (int i = tid; i < NTOK; i += blockDim.x) {
        int ty = ids[i];
        ty = ty < 0 ? 0 : (ty > T - 1 ? T - 1 : ty);
        int gd = e2g[ty];
        gid_s[i] = (unsigned char)gd;
        atomicAdd(&cnt[gd], 1);
    }
    __syncthreads();
    if (tid == 0) {
        int acc = 0;
        for (int e = 0; e < NE; e++) { g_gstart[e] = acc; cur[e] = acc; acc += cnt[e]; }
        g_gstart[NE] = acc;
    }
    __syncthreads();
    for (int i = tid; i < NTOK; i += blockDim.x) {
        int pos = atomicAdd(&cur[gid_s[i]], 1);
        g_perm[pos] = i;
    }
    if (tid < NE) g_alpha[tid] = 0.05f / (1.0f + expf(-raw_alpha[tid]));
}

// ---------------- weight transpose + fp32->bf16 convert ----------------
__global__ void transpose_kernel(const float* __restrict__ in, int R, int C, int which) {
    __shared__ float tile[32][33];
    __nv_bfloat16* out = which ? g_W2t : g_W1t;
    int e  = blockIdx.z;
    int c0 = blockIdx.x * 32, r0 = blockIdx.y * 32;
    const float* inp = in + (size_t)e * R * C;
    __nv_bfloat16* op = out + (size_t)e * R * C;
    int tx = threadIdx.x, ty = threadIdx.y;
    #pragma unroll
    for (int j = ty; j < 32; j += 8)
        tile[j][tx] = inp[(size_t)(r0 + j) * C + c0 + tx];
    __syncthreads();
    #pragma unroll
    for (int j = ty; j < 32; j += 8)
        op[(size_t)(c0 + j) * R + r0 + tx] = __float2bfloat16(tile[tx][j]);
}

// ---------------- bf16 warp MMA helper ----------------
__device__ __forceinline__ void mma16816(float* c, const uint32_t* a, const uint32_t* b) {
    asm volatile(
        "mma.sync.aligned.m16n8k16.row.col.f32.bf16.bf16.f32 "
        "{%0,%1,%2,%3}, {%4,%5,%6,%7}, {%8,%9}, {%0,%1,%2,%3};\n"
        : "+f"(c[0]), "+f"(c[1]), "+f"(c[2]), "+f"(c[3])
        : "r"(a[0]), "r"(a[1]), "r"(a[2]), "r"(a[3]), "r"(b[0]), "r"(b[1]));
}

// ---------------- grouped GEMM (2-stage cp.async pipeline) ----------------
// EPI2 == false : g_h[p,:] = relu(x[perm[p],:] @ W1[g] + b1[g])   (A loaded fp32+perm, fused gather)
// EPI2 == true  : g_pre[t,:] = x[t,:] + alpha[g] * (g_h[p,:] @ W2[g] + b2[g])
template<int K, bool EPI2>
__global__ void __launch_bounds__(256) gemm_kernel(
    const float* __restrict__ bias,   // [E][Ntot] fp32
    const float* __restrict__ x)
{
    constexpr int BM = 128, BN = 128, BK = 32, PAD = 8;
    constexpr int NTOT = EPI2 ? DDIM : HDIM;
    constexpr int NIT  = K / BK;
    __shared__ __align__(16) __nv_bfloat16 As[2][BM][BK + PAD];
    __shared__ __align__(16) __nv_bfloat16 Bs[2][BN][BK + PAD];

    const __nv_bfloat16* Bt = EPI2 ? g_W2t : g_W1t;

    int g     = blockIdx.z;
    int start = g_gstart[g];
    int cnt   = g_gstart[g + 1] - start;
    int m0    = blockIdx.x * BM;
    if (m0 >= cnt) return;
    int n0 = blockIdx.y * BN;
    const __nv_bfloat16* Bg = Bt + (size_t)g * NTOT * K;

    int tid  = threadIdx.x;
    int warp = tid >> 5, lane = tid & 31;
    int wm = (warp & 3) * 32;
    int wn = (warp >> 2) * 64;
    int lrow = lane >> 2;
    int lcol = (lane & 3) * 2;

    // ---- per-thread A-load geometry ----
    // GEMM1 (fp32 + perm): thread owns row = tid>>1, 16 floats at col half*16
    int arow  = tid >> 1;
    int ahalf = tid & 1;
    const float* aptr = nullptr;
    if (!EPI2) {
        if (m0 + arow < cnt)
            aptr = x + (size_t)g_perm[start + m0 + arow] * DDIM + ahalf * 16;
    }
    // GEMM2 (bf16 cp.async): 2 chunks of 8 bf16 per thread, chunk c: row=c>>2, v=c&3
    const __nv_bfloat16* Ag = EPI2 ? (g_h + (size_t)start * K) : nullptr;

    auto load_stage = [&](int s, int k0) {
        // B tile: 512 16B-chunks, 2 per thread
        #pragma unroll
        for (int i = 0; i < 2; i++) {
            int c = tid + i * 256;
            int r = c >> 2, v = c & 3;
            cp_async16(&Bs[s][r][v * 8], Bg + (size_t)(n0 + r) * K + k0 + v * 8, true);
        }
        if (EPI2) {
            #pragma unroll
            for (int i = 0; i < 2; i++) {
                int c = tid + i * 256;
                int r = c >> 2, v = c & 3;
                bool p = (m0 + r) < cnt;
                cp_async16(&As[s][r][v * 8],
                           Ag + (size_t)(m0 + r) * K + k0 + v * 8, p);
            }
        }
    };

    auto sts_a_fp32 = [&](int s, const float4* f4) {
        // 4 float4 -> 16 bf16 -> 2 uint4 STS
        uint4 o[2];
        #pragma unroll
        for (int j = 0; j < 2; j++) {
            __nv_bfloat162 h0 = __floats2bfloat162_rn(f4[2*j].x,   f4[2*j].y);
            __nv_bfloat162 h1 = __floats2bfloat162_rn(f4[2*j].z,   f4[2*j].w);
            __nv_bfloat162 h2 = __floats2bfloat162_rn(f4[2*j+1].x, f4[2*j+1].y);
            __nv_bfloat162 h3 = __floats2bfloat162_rn(f4[2*j+1].z, f4[2*j+1].w);
            o[j].x = *reinterpret_cast<uint32_t*>(&h0);
            o[j].y = *reinterpret_cast<uint32_t*>(&h1);
            o[j].z = *reinterpret_cast<uint32_t*>(&h2);
            o[j].w = *reinterpret_cast<uint32_t*>(&h3);
        }
        uint4* dst = reinterpret_cast<uint4*>(&As[s][arow][ahalf * 16]);
        dst[0] = o[0];
        dst[1] = o[1];
    };

    float acc[2][8][4];
    #pragma unroll
    for (int mi = 0; mi < 2; mi++)
        #pragma unroll
        for (int ni = 0; ni < 8; ni++)
            #pragma unroll
            for (int q = 0; q < 4; q++) acc[mi][ni][q] = 0.f;

    // ---- prologue: stage 0 ----
    load_stage(0, 0);
    if (!EPI2) {
        float4 f4[4] = {};
        if (aptr) {
            #pragma unroll
            for (int j = 0; j < 4; j++)
                f4[j] = *reinterpret_cast<const float4*>(aptr + j * 4);
        }
        sts_a_fp32(0, f4);
    }
    CP_COMMIT();

    for (int it = 0; it < NIT; it++) {
        int cur = it & 1, nxt = cur ^ 1;
        CP_WAIT0();
        __syncthreads();

        bool more = (it + 1) < NIT;
        if (more) {
            load_stage(nxt, (it + 1) * BK);
            CP_COMMIT();
        }
        // issue next-stage A LDGs early (overlap with MMA below)
        float4 f4[4] = {};
        if (!EPI2 && more && aptr) {
            #pragma unroll
            for (int j = 0; j < 4; j++)
                f4[j] = *reinterpret_cast<const float4*>(aptr + (it + 1) * BK + j * 4);
        }

        // ---- compute current stage ----
        #pragma unroll
        for (int kk = 0; kk < BK; kk += 16) {
            uint32_t af[2][4], bfr[8][2];
            #pragma unroll
            for (int mi = 0; mi < 2; mi++) {
                int r = wm + mi * 16;
                af[mi][0] = *reinterpret_cast<const uint32_t*>(&As[cur][r + lrow    ][kk + lcol    ]);
                af[mi][1] = *reinterpret_cast<const uint32_t*>(&As[cur][r + lrow + 8][kk + lcol    ]);
                af[mi][2] = *reinterpret_cast<const uint32_t*>(&As[cur][r + lrow    ][kk + lcol + 8]);
                af[mi][3] = *reinterpret_cast<const uint32_t*>(&As[cur][r + lrow + 8][kk + lcol + 8]);
            }
            #pragma unroll
            for (int ni = 0; ni < 8; ni++) {
                int c = wn + ni * 8 + lrow;
                bfr[ni][0] = *reinterpret_cast<const uint32_t*>(&Bs[cur][c][kk + lcol    ]);
                bfr[ni][1] = *reinterpret_cast<const uint32_t*>(&Bs[cur][c][kk + lcol + 8]);
            }
            #pragma unroll
            for (int mi = 0; mi < 2; mi++)
                #pragma unroll
                for (int ni = 0; ni < 8; ni++)
                    mma16816(acc[mi][ni], af[mi], bfr[ni]);
        }

        if (!EPI2 && more) sts_a_fp32(nxt, f4);
    }

    // ---- epilogue ----
    float alpha = EPI2 ? g_alpha[g] : 0.f;
    const float* bg = bias + (size_t)g * NTOT;
    #pragma unroll
    for (int mi = 0; mi < 2; mi++) {
        #pragma unroll
        for (int half = 0; half < 2; half++) {
            int rloc = wm + mi * 16 + lrow + half * 8;
            int grow = m0 + rloc;
            if (grow >= cnt) continue;
            #pragma unroll
            for (int ni = 0; ni < 8; ni++) {
                int c = n0 + wn + ni * 8 + lcol;
                float v0 = acc[mi][ni][half * 2 + 0] + bg[c];
                float v1 = acc[mi][ni][half * 2 + 1] + bg[c + 1];
                if (!EPI2) {
                    v0 = fmaxf(v0, 0.f);
                    v1 = fmaxf(v1, 0.f);
                    __nv_bfloat162 pk = __floats2bfloat162_rn(v0, v1);
                    *reinterpret_cast<__nv_bfloat162*>(
                        &g_h[(size_t)(start + grow) * HDIM + c]) = pk;
                } else {
                    int t = g_perm[start + grow];
                    float2 xv = *reinterpret_cast<const float2*>(x + (size_t)t * DDIM + c);
                    float2 o;
                    o.x = xv.x + alpha * v0;
                    o.y = xv.y + alpha * v1;
                    *reinterpret_cast<float2*>(&g_pre[(size_t)t * DDIM + c]) = o;
                }
            }
        }
    }
}

// ---------------- normalize: out = pre / max(||pre||, 1e-12) ----------------
__global__ void normalize_kernel(float* __restrict__ out) {
    int t = blockIdx.x;
    const float4* pr = reinterpret_cast<const float4*>(g_pre) + (size_t)t * 192;
    float4 v = pr[threadIdx.x];
    float s = v.x * v.x + v.y * v.y + v.z * v.z + v.w * v.w;
    #pragma unroll
    for (int o = 16; o > 0; o >>= 1) s += __shfl_xor_sync(0xffffffffu, s, o);
    __shared__ float red[6];
    int warp = threadIdx.x >> 5, lane = threadIdx.x & 31;
    if (lane == 0) red[warp] = s;
    __syncthreads();
    if (threadIdx.x == 0) {
        float z = 0.f;
        #pragma unroll
        for (int i = 0; i < 6; i++) z += red[i];
        red[0] = 1.f / fmaxf(sqrtf(z), 1e-12f);
    }
    __syncthreads();
    float inv = red[0];
    float4 o;
    o.x = v.x * inv; o.y = v.y * inv; o.z = v.z * inv; o.w = v.w * inv;
    reinterpret_cast<float4*>(out)[(size_t)t * 192 + threadIdx.x] = o;
}

// ---------------- launch ----------------
extern "C" void kernel_launch(void* const* d_in, const int* in_sizes, int n_in,
                              void* d_out, int out_size) {
    const float* x         = (const float*)d_in[0];
    const int*   ids       = (const int*)d_in[1];
    const float* W1        = (const float*)d_in[2];
    const float* b1        = (const float*)d_in[3];
    const float* W2        = (const float*)d_in[4];
    const float* b2        = (const float*)d_in[5];
    const float* raw_alpha = (const float*)d_in[6];
    const int*   e2g       = (const int*)d_in[7];
    int T = in_sizes[7];

    prep_kernel<<<1, 256>>>(ids, e2g, raw_alpha, T);

    transpose_kernel<<<dim3(HDIM / 32, DDIM / 32, NE), dim3(32, 8)>>>(W1, DDIM, HDIM, 0);
    transpose_kernel<<<dim3(DDIM / 32, HDIM / 32, NE), dim3(32, 8)>>>(W2, HDIM, DDIM, 1);

    // GEMM1: fused gather (x fp32 + perm) -> relu -> g_h
    gemm_kernel<DDIM, false><<<dim3(NTOK / 128, HDIM / 128, NE), 256>>>(b1, x);
    // GEMM2: g_h @ W2 + b2 -> x + alpha*r -> g_pre (token order)
    gemm_kernel<HDIM, true ><<<dim3(NTOK / 128, DDIM / 128, NE), 256>>>(b2, x);

    normalize_kernel<<<NTOK, 192>>>((float*)d_out);
}

// round 3
// speedup vs baseline: 1.2362x; 1.1102x over previous
#include <cuda_runtime.h>
#include <cuda_bf16.h>
#include <cstdint>
#include <math.h>

#define NTOK 4096
#define DDIM 768
#define HDIM 1536
#define NE   6

// ---------------- device scratch ----------------
__device__ int   g_perm[NTOK];
__device__ int   g_gstart[NE + 1];
__device__ float g_alpha[NE];
__device__ __nv_bfloat16 g_xg[(size_t)NTOK * DDIM];          // gathered x, perm order (bf16)
__device__ __nv_bfloat16 g_h [(size_t)NTOK * HDIM];          // relu hidden, perm order
__device__ __nv_bfloat16 g_W1t[(size_t)NE * HDIM * DDIM];    // [e][h][d]
__device__ __nv_bfloat16 g_W2t[(size_t)NE * DDIM * HDIM];    // [e][d][h]
__device__ float g_pre[(size_t)NTOK * DDIM];                 // x + alpha*r, token order

// ---------------- asm helpers ----------------
__device__ __forceinline__ void cp_async16(void* smem, const void* g, bool pred) {
    uint32_t s = (uint32_t)__cvta_generic_to_shared(smem);
    int sz = pred ? 16 : 0;   // src-size 0 -> 16B zero-fill
    asm volatile("cp.async.cg.shared.global [%0], [%1], 16, %2;\n" :: "r"(s), "l"(g), "r"(sz));
}
#define CP_COMMIT() asm volatile("cp.async.commit_group;\n" ::: "memory")
#define CP_WAIT1()  asm volatile("cp.async.wait_group 1;\n" ::: "memory")

__device__ __forceinline__ void ldsm_x4(uint32_t& r0, uint32_t& r1, uint32_t& r2, uint32_t& r3,
                                        uint32_t addr) {
    asm volatile("ldmatrix.sync.aligned.m8n8.x4.shared.b16 {%0,%1,%2,%3}, [%4];"
                 : "=r"(r0), "=r"(r1), "=r"(r2), "=r"(r3) : "r"(addr));
}

__device__ __forceinline__ void mma16816(float* c, const uint32_t* a, const uint32_t* b) {
    asm volatile(
        "mma.sync.aligned.m16n8k16.row.col.f32.bf16.bf16.f32 "
        "{%0,%1,%2,%3}, {%4,%5,%6,%7}, {%8,%9}, {%0,%1,%2,%3};\n"
        : "+f"(c[0]), "+f"(c[1]), "+f"(c[2]), "+f"(c[3])
        : "r"(a[0]), "r"(a[1]), "r"(a[2]), "r"(a[3]), "r"(b[0]), "r"(b[1]));
}

// ---------------- prep: sort tokens by group ----------------
__global__ void prep_kernel(const int* __restrict__ ids,
                            const int* __restrict__ e2g,
                            const float* __restrict__ raw_alpha,
                            int T) {
    __shared__ int cnt[NE];
    __shared__ int cur[NE];
    __shared__ unsigned char gid_s[NTOK];
    int tid = threadIdx.x;
    if (tid < NE) cnt[tid] = 0;
    __syncthreads();
    for (int i = tid; i < NTOK; i += blockDim.x) {
        int ty = ids[i];
        ty = ty < 0 ? 0 : (ty > T - 1 ? T - 1 : ty);
        int gd = e2g[ty];
        gid_s[i] = (unsigned char)gd;
        atomicAdd(&cnt[gd], 1);
    }
    __syncthreads();
    if (tid == 0) {
        int acc = 0;
        for (int e = 0; e < NE; e++) { g_gstart[e] = acc; cur[e] = acc; acc += cnt[e]; }
        g_gstart[NE] = acc;
    }
    __syncthreads();
    for (int i = tid; i < NTOK; i += blockDim.x) {
        int pos = atomicAdd(&cur[gid_s[i]], 1);
        g_perm[pos] = i;
    }
    if (tid < NE) g_alpha[tid] = 0.05f / (1.0f + expf(-raw_alpha[tid]));
}

// ---------------- weight transpose + fp32->bf16 ----------------
__global__ void transpose_kernel(const float* __restrict__ in, int R, int C, int which) {
    __shared__ float tile[32][33];
    __nv_bfloat16* out = which ? g_W2t : g_W1t;
    int e  = blockIdx.z;
    int c0 = blockIdx.x * 32, r0 = blockIdx.y * 32;
    const float* inp = in + (size_t)e * R * C;
    __nv_bfloat16* op = out + (size_t)e * R * C;
    int tx = threadIdx.x, ty = threadIdx.y;
    #pragma unroll
    for (int j = ty; j < 32; j += 8)
        tile[j][tx] = inp[(size_t)(r0 + j) * C + c0 + tx];
    __syncthreads();
    #pragma unroll
    for (int j = ty; j < 32; j += 8)
        op[(size_t)(c0 + j) * R + r0 + tx] = __float2bfloat16(tile[tx][j]);
}

// ---------------- gather x rows in perm order (fp32 -> bf16, float4) ----------------
// 384 blocks x 256 threads x 8 float4 = 786432 float4 = 4096 rows * 192
__global__ void gather_kernel(const float* __restrict__ x) {
    int idx0 = blockIdx.x * 256 + threadIdx.x;
    #pragma unroll
    for (int i = 0; i < 8; i++) {
        int idx = idx0 + i * 98304;
        int p = idx / 192, j = idx % 192;
        int t = g_perm[p];
        float4 v = *(reinterpret_cast<const float4*>(x + (size_t)t * DDIM) + j);
        __nv_bfloat162 h0 = __floats2bfloat162_rn(v.x, v.y);
        __nv_bfloat162 h1 = __floats2bfloat162_rn(v.z, v.w);
        uint2 o;
        o.x = *reinterpret_cast<uint32_t*>(&h0);
        o.y = *reinterpret_cast<uint32_t*>(&h1);
        *(reinterpret_cast<uint2*>(g_xg + (size_t)p * DDIM) + j) = o;
    }
}

// ---------------- grouped GEMM: 3-stage cp.async + ldmatrix ----------------
// EPI2 == false : g_h[p,:] = relu(g_xg[p,:] @ W1[g] + b1[g])   bf16 out
// EPI2 == true  : g_pre[t,:] = x[t,:] + alpha[g] * (g_h[p,:] @ W2[g] + b2[g])
template<int K, bool EPI2>
__global__ void __launch_bounds__(256) gemm_kernel(
    const float* __restrict__ bias,
    const float* __restrict__ x)
{
    constexpr int BM = 128, BN = 128, BK = 32, LDT = 40;     // LDT: smem row pitch (bf16)
    constexpr int NTOT = EPI2 ? DDIM : HDIM;
    constexpr int NIT  = K / BK;
    constexpr int STAGE_ELEMS = (BM + BN) * LDT;              // 10240 bf16
    constexpr int STAGE_BYTES = STAGE_ELEMS * 2;              // 20480
    constexpr int B_BYTE_OFF  = BM * LDT * 2;                 // 10240

    extern __shared__ __align__(16) unsigned char smem_raw[];
    __nv_bfloat16* smem = reinterpret_cast<__nv_bfloat16*>(smem_raw);
    uint32_t sbase = (uint32_t)__cvta_generic_to_shared(smem_raw);

    const __nv_bfloat16* A  = EPI2 ? g_h   : g_xg;
    const __nv_bfloat16* Bt = EPI2 ? g_W2t : g_W1t;

    int g     = blockIdx.z;
    int start = g_gstart[g];
    int cnt   = g_gstart[g + 1] - start;
    int m0    = blockIdx.x * BM;
    if (m0 >= cnt) return;
    int n0 = blockIdx.y * BN;
    const __nv_bfloat16* Bg = Bt + (size_t)g * NTOT * K;
    const __nv_bfloat16* Ag = A + (size_t)start * K;

    int tid  = threadIdx.x;
    int warp = tid >> 5, lane = tid & 31;
    int wm = (warp & 3) * 32;
    int wn = (warp >> 2) * 64;
    int lrow = lane >> 2;
    int lcol = (lane & 3) * 2;

    // ldmatrix per-lane byte offsets (within a stage)
    int l15 = lane & 15, lhi = lane >> 4;
    uint32_t aOff[2];
    #pragma unroll
    for (int mi = 0; mi < 2; mi++)
        aOff[mi] = (uint32_t)(((wm + mi * 16 + l15) * LDT + lhi * 8) * 2);
    int q = lane >> 3, rB = lane & 7;
    uint32_t bOff[4];
    #pragma unroll
    for (int j = 0; j < 4; j++)
        bOff[j] = (uint32_t)(B_BYTE_OFF + ((wn + j * 16 + (q >> 1) * 8 + rB) * LDT + (q & 1) * 8) * 2);

    auto load_stage = [&](int s, int k0) {
        __nv_bfloat16* As = smem + s * STAGE_ELEMS;
        __nv_bfloat16* Bs = As + BM * LDT;
        #pragma unroll
        for (int i = 0; i < 2; i++) {
            int c = tid + i * 256;
            int r = c >> 2, v = c & 3;
            cp_async16(&Bs[r * LDT + v * 8], Bg + (size_t)(n0 + r) * K + k0 + v * 8, true);
        }
        #pragma unroll
        for (int i = 0; i < 2; i++) {
            int c = tid + i * 256;
            int r = c >> 2, v = c & 3;
            bool p = (m0 + r) < cnt;
            int rr = p ? (m0 + r) : (cnt - 1);   // clamp address, pred zero-fills
            cp_async16(&As[r * LDT + v * 8], Ag + (size_t)rr * K + k0 + v * 8, p);
        }
    };

    float acc[2][8][4];
    #pragma unroll
    for (int mi = 0; mi < 2; mi++)
        #pragma unroll
        for (int ni = 0; ni < 8; ni++)
            #pragma unroll
            for (int qq = 0; qq < 4; qq++) acc[mi][ni][qq] = 0.f;

    // prologue: 2 stages in flight
    load_stage(0, 0);
    CP_COMMIT();
    load_stage(1, BK);
    CP_COMMIT();

    for (int it = 0; it < NIT; it++) {
        CP_WAIT1();
        __syncthreads();

        if (it + 2 < NIT) load_stage((it + 2) % 3, (it + 2) * BK);
        CP_COMMIT();

        uint32_t stg = sbase + (uint32_t)((it % 3) * STAGE_BYTES);
        #pragma unroll
        for (int kk = 0; kk < BK; kk += 16) {
            uint32_t af[2][4], bq[4][4];
            #pragma unroll
            for (int mi = 0; mi < 2; mi++)
                ldsm_x4(af[mi][0], af[mi][1], af[mi][2], af[mi][3],
                        stg + aOff[mi] + kk * 2);
            #pragma unroll
            for (int j = 0; j < 4; j++)
                ldsm_x4(bq[j][0], bq[j][1], bq[j][2], bq[j][3],
                        stg + bOff[j] + kk * 2);
            #pragma unroll
            for (int mi = 0; mi < 2; mi++)
                #pragma unroll
                for (int ni = 0; ni < 8; ni++)
                    mma16816(acc[mi][ni], af[mi], &bq[ni >> 1][(ni & 1) * 2]);
        }
    }

    // ---- epilogue ----
    float alpha = EPI2 ? g_alpha[g] : 0.f;
    const float* bg = bias + (size_t)g * NTOT;
    #pragma unroll
    for (int mi = 0; mi < 2; mi++) {
        #pragma unroll
        for (int half = 0; half < 2; half++) {
            int rloc = wm + mi * 16 + lrow + half * 8;
            int grow = m0 + rloc;
            if (grow >= cnt) continue;
            #pragma unroll
            for (int ni = 0; ni < 8; ni++) {
                int c = n0 + wn + ni * 8 + lcol;
                float v0 = acc[mi][ni][half * 2 + 0] + bg[c];
                float v1 = acc[mi][ni][half * 2 + 1] + bg[c + 1];
                if (!EPI2) {
                    v0 = fmaxf(v0, 0.f);
                    v1 = fmaxf(v1, 0.f);
                    __nv_bfloat162 pk = __floats2bfloat162_rn(v0, v1);
                    *reinterpret_cast<__nv_bfloat162*>(
                        &g_h[(size_t)(start + grow) * HDIM + c]) = pk;
                } else {
                    int t = g_perm[start + grow];
                    float2 xv = *reinterpret_cast<const float2*>(x + (size_t)t * DDIM + c);
                    float2 o;
                    o.x = xv.x + alpha * v0;
                    o.y = xv.y + alpha * v1;
                    *reinterpret_cast<float2*>(&g_pre[(size_t)t * DDIM + c]) = o;
                }
            }
        }
    }
}

// ---------------- normalize ----------------
__global__ void normalize_kernel(float* __restrict__ out) {
    int t = blockIdx.x;
    const float4* pr = reinterpret_cast<const float4*>(g_pre) + (size_t)t * 192;
    float4 v = pr[threadIdx.x];
    float s = v.x * v.x + v.y * v.y + v.z * v.z + v.w * v.w;
    #pragma unroll
    for (int o = 16; o > 0; o >>= 1) s += __shfl_xor_sync(0xffffffffu, s, o);
    __shared__ float red[6];
    int warp = threadIdx.x >> 5, lane = threadIdx.x & 31;
    if (lane == 0) red[warp] = s;
    __syncthreads();
    if (threadIdx.x == 0) {
        float z = 0.f;
        #pragma unroll
        for (int i = 0; i < 6; i++) z += red[i];
        red[0] = 1.f / fmaxf(sqrtf(z), 1e-12f);
    }
    __syncthreads();
    float inv = red[0];
    float4 o;
    o.x = v.x * inv; o.y = v.y * inv; o.z = v.z * inv; o.w = v.w * inv;
    reinterpret_cast<float4*>(out)[(size_t)t * 192 + threadIdx.x] = o;
}

// ---------------- launch ----------------
extern "C" void kernel_launch(void* const* d_in, const int* in_sizes, int n_in,
                              void* d_out, int out_size) {
    const float* x         = (const float*)d_in[0];
    const int*   ids       = (const int*)d_in[1];
    const float* W1        = (const float*)d_in[2];
    const float* b1        = (const float*)d_in[3];
    const float* W2        = (const float*)d_in[4];
    const float* b2        = (const float*)d_in[5];
    const float* raw_alpha = (const float*)d_in[6];
    const int*   e2g       = (const int*)d_in[7];
    int T = in_sizes[7];

    constexpr int SMEM_GEMM = (128 + 128) * 40 * 2 * 3;   // 61440 B
    cudaFuncSetAttribute(gemm_kernel<DDIM, false>,
                         cudaFuncAttributeMaxDynamicSharedMemorySize, SMEM_GEMM);
    cudaFuncSetAttribute(gemm_kernel<HDIM, true>,
                         cudaFuncAttributeMaxDynamicSharedMemorySize, SMEM_GEMM);

    prep_kernel<<<1, 256>>>(ids, e2g, raw_alpha, T);

    transpose_kernel<<<dim3(HDIM / 32, DDIM / 32, NE), dim3(32, 8)>>>(W1, DDIM, HDIM, 0);
    transpose_kernel<<<dim3(DDIM / 32, HDIM / 32, NE), dim3(32, 8)>>>(W2, HDIM, DDIM, 1);

    gather_kernel<<<384, 256>>>(x);

    gemm_kernel<DDIM, false><<<dim3(NTOK / 128, HDIM / 128, NE), 256, SMEM_GEMM>>>(b1, x);
    gemm_kernel<HDIM, true ><<<dim3(NTOK / 128, DDIM / 128, NE), 256, SMEM_GEMM>>>(b2, x);

    normalize_kernel<<<NTOK, 192>>>((float*)d_out);
}

// round 5
// speedup vs baseline: 1.5202x; 1.2297x over previous
#include <cuda_runtime.h>
#include <cuda_bf16.h>
#include <cstdint>
#include <math.h>

#define NTOK 4096
#define DDIM 768
#define HDIM 1536
#define NE   6

// ---------------- device scratch ----------------
__device__ int   g_perm[NTOK];
__device__ int   g_gstart[NE + 1];
__device__ float g_alpha[NE];
__device__ __nv_bfloat16 g_xg[(size_t)NTOK * DDIM];          // gathered x, perm order (bf16)
__device__ __nv_bfloat16 g_h [(size_t)NTOK * HDIM];          // relu hidden, perm order
__device__ __nv_bfloat16 g_W1b[(size_t)NE * DDIM * HDIM];    // bf16 copy of W1, native [e][d][h]
__device__ __nv_bfloat16 g_W2b[(size_t)NE * HDIM * DDIM];    // bf16 copy of W2, native [e][h][d]
__device__ float g_pre[(size_t)NTOK * DDIM];                 // x + alpha*r, token order

// ---------------- asm helpers ----------------
__device__ __forceinline__ void cp_async16(void* smem, const void* g, bool pred) {
    uint32_t s = (uint32_t)__cvta_generic_to_shared(smem);
    int sz = pred ? 16 : 0;   // src-size 0 -> 16B zero-fill
    asm volatile("cp.async.cg.shared.global [%0], [%1], 16, %2;\n" :: "r"(s), "l"(g), "r"(sz));
}
#define CP_COMMIT() asm volatile("cp.async.commit_group;\n" ::: "memory")
#define CP_WAIT1()  asm volatile("cp.async.wait_group 1;\n" ::: "memory")

__device__ __forceinline__ void ldsm_x4(uint32_t& r0, uint32_t& r1, uint32_t& r2, uint32_t& r3,
                                        uint32_t addr) {
    asm volatile("ldmatrix.sync.aligned.m8n8.x4.shared.b16 {%0,%1,%2,%3}, [%4];"
                 : "=r"(r0), "=r"(r1), "=r"(r2), "=r"(r3) : "r"(addr));
}
__device__ __forceinline__ void ldsm_x4_t(uint32_t& r0, uint32_t& r1, uint32_t& r2, uint32_t& r3,
                                          uint32_t addr) {
    asm volatile("ldmatrix.sync.aligned.m8n8.x4.trans.shared.b16 {%0,%1,%2,%3}, [%4];"
                 : "=r"(r0), "=r"(r1), "=r"(r2), "=r"(r3) : "r"(addr));
}

__device__ __forceinline__ void mma16816(float* c, const uint32_t* a, const uint32_t* b) {
    asm volatile(
        "mma.sync.aligned.m16n8k16.row.col.f32.bf16.bf16.f32 "
        "{%0,%1,%2,%3}, {%4,%5,%6,%7}, {%8,%9}, {%0,%1,%2,%3};\n"
        : "+f"(c[0]), "+f"(c[1]), "+f"(c[2]), "+f"(c[3])
        : "r"(a[0]), "r"(a[1]), "r"(a[2]), "r"(a[3]), "r"(b[0]), "r"(b[1]));
}

// ---------------- prep: sort tokens by group ----------------
__global__ void prep_kernel(const int* __restrict__ ids,
                            const int* __restrict__ e2g,
                            const float* __restrict__ raw_alpha,
                            int T) {
    __shared__ int cnt[NE];
    __shared__ int cur[NE];
    __shared__ unsigned char gid_s[NTOK];
    int tid = threadIdx.x;
    if (tid < NE) cnt[tid] = 0;
    __syncthreads();
    for (int i = tid; i < NTOK; i += blockDim.x) {
        int ty = ids[i];
        ty = ty < 0 ? 0 : (ty > T - 1 ? T - 1 : ty);
        int gd = e2g[ty];
        gid_s[i] = (unsigned char)gd;
        atomicAdd(&cnt[gd], 1);
    }
    __syncthreads();
    if (tid == 0) {
        int acc = 0;
        for (int e = 0; e < NE; e++) { g_gstart[e] = acc; cur[e] = acc; acc += cnt[e]; }
        g_gstart[NE] = acc;
    }
    __syncthreads();
    for (int i = tid; i < NTOK; i += blockDim.x) {
        int pos = atomicAdd(&cur[gid_s[i]], 1);
        g_perm[pos] = i;
    }
    if (tid < NE) g_alpha[tid] = 0.05f / (1.0f + expf(-raw_alpha[tid]));
}

// ---------------- streaming fp32 -> bf16 weight convert (no transpose) ----------------
// n = NE*DDIM*HDIM = 7077888 elems per weight; 8 elems per thread
__global__ void convert_kernel(const float* __restrict__ in, int which) {
    __nv_bfloat16* out = which ? g_W2b : g_W1b;
    size_t i0 = ((size_t)blockIdx.x * 256 + threadIdx.x) * 8;
    float4 a = *reinterpret_cast<const float4*>(in + i0);
    float4 b = *reinterpret_cast<const float4*>(in + i0 + 4);
    __nv_bfloat162 h0 = __floats2bfloat162_rn(a.x, a.y);
    __nv_bfloat162 h1 = __floats2bfloat162_rn(a.z, a.w);
    __nv_bfloat162 h2 = __floats2bfloat162_rn(b.x, b.y);
    __nv_bfloat162 h3 = __floats2bfloat162_rn(b.z, b.w);
    uint4 o;
    o.x = *reinterpret_cast<uint32_t*>(&h0);
    o.y = *reinterpret_cast<uint32_t*>(&h1);
    o.z = *reinterpret_cast<uint32_t*>(&h2);
    o.w = *reinterpret_cast<uint32_t*>(&h3);
    *reinterpret_cast<uint4*>(out + i0) = o;
}

// ---------------- gather: one float4 per thread, fully parallel ----------------
// 3072 blocks x 256 threads = 786432 = 4096 rows * 192 float4
__global__ void gather_kernel(const float* __restrict__ x) {
    int idx = blockIdx.x * 256 + threadIdx.x;
    int p = idx / 192, j = idx % 192;
    int t = g_perm[p];
    float4 v = *(reinterpret_cast<const float4*>(x + (size_t)t * DDIM) + j);
    __nv_bfloat162 h0 = __floats2bfloat162_rn(v.x, v.y);
    __nv_bfloat162 h1 = __floats2bfloat162_rn(v.z, v.w);
    uint2 o;
    o.x = *reinterpret_cast<uint32_t*>(&h0);
    o.y = *reinterpret_cast<uint32_t*>(&h1);
    *(reinterpret_cast<uint2*>(g_xg + (size_t)p * DDIM) + j) = o;
}

// ---------------- grouped GEMM: 3-stage cp.async, A ldmatrix, B ldmatrix.trans ----------------
// B consumed natively k-major: W1 [d][h] for GEMM1, W2 [h][d] for GEMM2.
// EPI2 == false : g_h[p,:] = relu(g_xg[p,:] @ W1[g] + b1[g])   bf16 out
// EPI2 == true  : g_pre[t,:] = x[t,:] + alpha[g] * (g_h[p,:] @ W2[g] + b2[g])
template<int K, bool EPI2>
__global__ void __launch_bounds__(256) gemm_kernel(
    const float* __restrict__ bias,
    const float* __restrict__ x)
{
    constexpr int BM = 128, BN = 128, BK = 32;
    constexpr int LDA = 40;                        // A smem pitch (bf16)
    constexpr int LDB = 136;                       // B smem pitch (bf16), 272B rows
    constexpr int NTOT = EPI2 ? DDIM : HDIM;       // n-extent of this GEMM
    constexpr int NIT  = K / BK;
    constexpr int A_ELEMS = BM * LDA;              // 5120
    constexpr int STAGE_ELEMS = A_ELEMS + BK * LDB;   // 5120 + 4352 = 9472
    constexpr int STAGE_BYTES = STAGE_ELEMS * 2;   // 18944
    constexpr int B_BYTE_OFF  = A_ELEMS * 2;       // 10240

    extern __shared__ __align__(16) unsigned char smem_raw[];
    __nv_bfloat16* smem = reinterpret_cast<__nv_bfloat16*>(smem_raw);
    uint32_t sbase = (uint32_t)__cvta_generic_to_shared(smem_raw);

    const __nv_bfloat16* A  = EPI2 ? g_h   : g_xg;
    const __nv_bfloat16* Bw = EPI2 ? g_W2b : g_W1b;

    int g     = blockIdx.z;
    int start = g_gstart[g];
    int cnt   = g_gstart[g + 1] - start;
    int m0    = blockIdx.x * BM;
    if (m0 >= cnt) return;
    int n0 = blockIdx.y * BN;
    const __nv_bfloat16* Bg = Bw + (size_t)g * K * NTOT;   // [K][NTOT] k-major
    const __nv_bfloat16* Ag = A + (size_t)start * K;

    int tid  = threadIdx.x;
    int warp = tid >> 5, lane = tid & 31;
    int wm = (warp & 3) * 32;
    int wn = (warp >> 2) * 64;
    int lrow = lane >> 2;
    int lcol = (lane & 3) * 2;

    int l15 = lane & 15, lhi = lane >> 4;
    uint32_t aOff[2];
    #pragma unroll
    for (int mi = 0; mi < 2; mi++)
        aOff[mi] = (uint32_t)(((wm + mi * 16 + l15) * LDA + lhi * 8) * 2);
    // B (trans): lane l -> k-row (l&15), n-col (wn + j*16 + (l>>4)*8)
    uint32_t bOff[4];
    #pragma unroll
    for (int j = 0; j < 4; j++)
        bOff[j] = (uint32_t)(B_BYTE_OFF + (l15 * LDB + wn + j * 16 + lhi * 8) * 2);

    auto load_stage = [&](int s, int k0) {
        __nv_bfloat16* As = smem + s * STAGE_ELEMS;
        __nv_bfloat16* Bs = As + A_ELEMS;
        // A: 128 rows x 4 chunks of 8 bf16
        #pragma unroll
        for (int i = 0; i < 2; i++) {
            int c = tid + i * 256;
            int r = c >> 2, v = c & 3;
            bool p = (m0 + r) < cnt;
            int rr = p ? (m0 + r) : 0;
            cp_async16(&As[r * LDA + v * 8], Ag + (size_t)rr * K + k0 + v * 8, p);
        }
        // B: 32 k-rows x 16 chunks of 8 bf16 (n contiguous)
        #pragma unroll
        for (int i = 0; i < 2; i++) {
            int c = tid + i * 256;
            int r = c >> 4, v = c & 15;
            cp_async16(&Bs[r * LDB + v * 8],
                       Bg + (size_t)(k0 + r) * NTOT + n0 + v * 8, true);
        }
    };

    float acc[2][8][4];
    #pragma unroll
    for (int mi = 0; mi < 2; mi++)
        #pragma unroll
        for (int ni = 0; ni < 8; ni++)
            #pragma unroll
            for (int qq = 0; qq < 4; qq++) acc[mi][ni][qq] = 0.f;

    load_stage(0, 0);
    CP_COMMIT();
    load_stage(1, BK);
    CP_COMMIT();

    for (int it = 0; it < NIT; it++) {
        CP_WAIT1();
        __syncthreads();

        if (it + 2 < NIT) load_stage((it + 2) % 3, (it + 2) * BK);
        CP_COMMIT();

        uint32_t stg = sbase + (uint32_t)((it % 3) * STAGE_BYTES);
        #pragma unroll
        for (int kk = 0; kk < BK; kk += 16) {
            uint32_t af[2][4], bq[4][4];
            #pragma unroll
            for (int mi = 0; mi < 2; mi++)
                ldsm_x4(af[mi][0], af[mi][1], af[mi][2], af[mi][3],
                        stg + aOff[mi] + kk * 2);
            #pragma unroll
            for (int j = 0; j < 4; j++)
                ldsm_x4_t(bq[j][0], bq[j][1], bq[j][2], bq[j][3],
                          stg + bOff[j] + kk * (LDB * 2));
            #pragma unroll
            for (int mi = 0; mi < 2; mi++)
                #pragma unroll
                for (int ni = 0; ni < 8; ni++)
                    mma16816(acc[mi][ni], af[mi], &bq[ni >> 1][(ni & 1) * 2]);
        }
    }

    // ---- epilogue ----
    float alpha = EPI2 ? g_alpha[g] : 0.f;
    const float* bg = bias + (size_t)g * NTOT;
    #pragma unroll
    for (int mi = 0; mi < 2; mi++) {
        #pragma unroll
        for (int half = 0; half < 2; half++) {
            int rloc = wm + mi * 16 + lrow + half * 8;
            int grow = m0 + rloc;
            if (grow >= cnt) continue;
            #pragma unroll
            for (int ni = 0; ni < 8; ni++) {
                int c = n0 + wn + ni * 8 + lcol;
                float v0 = acc[mi][ni][half * 2 + 0] + bg[c];
                float v1 = acc[mi][ni][half * 2 + 1] + bg[c + 1];
                if (!EPI2) {
                    v0 = fmaxf(v0, 0.f);
                    v1 = fmaxf(v1, 0.f);
                    __nv_bfloat162 pk = __floats2bfloat162_rn(v0, v1);
                    *reinterpret_cast<__nv_bfloat162*>(
                        &g_h[(size_t)(start + grow) * HDIM + c]) = pk;
                } else {
                    int t = g_perm[start + grow];
                    float2 xv = *reinterpret_cast<const float2*>(x + (size_t)t * DDIM + c);
                    float2 o;
                    o.x = xv.x + alpha * v0;
                    o.y = xv.y + alpha * v1;
                    *reinterpret_cast<float2*>(&g_pre[(size_t)t * DDIM + c]) = o;
                }
            }
        }
    }
}

// ---------------- normalize ----------------
__global__ void normalize_kernel(float* __restrict__ out) {
    int t = blockIdx.x;
    const float4* pr = reinterpret_cast<const float4*>(g_pre) + (size_t)t * 192;
    float4 v = pr[threadIdx.x];
    float s = v.x * v.x + v.y * v.y + v.z * v.z + v.w * v.w;
    #pragma unroll
    for (int o = 16; o > 0; o >>= 1) s += __shfl_xor_sync(0xffffffffu, s, o);
    __shared__ float red[6];
    int warp = threadIdx.x >> 5, lane = threadIdx.x & 31;
    if (lane == 0) red[warp] = s;
    __syncthreads();
    if (threadIdx.x == 0) {
        float z = 0.f;
        #pragma unroll
        for (int i = 0; i < 6; i++) z += red[i];
        red[0] = 1.f / fmaxf(sqrtf(z), 1e-12f);
    }
    __syncthreads();
    float inv = red[0];
    float4 o;
    o.x = v.x * inv; o.y = v.y * inv; o.z = v.z * inv; o.w = v.w * inv;
    reinterpret_cast<float4*>(out)[(size_t)t * 192 + threadIdx.x] = o;
}

// ---------------- launch ----------------
extern "C" void kernel_launch(void* const* d_in, const int* in_sizes, int n_in,
                              void* d_out, int out_size) {
    const float* x         = (const float*)d_in[0];
    const int*   ids       = (const int*)d_in[1];
    const float* W1        = (const float*)d_in[2];
    const float* b1        = (const float*)d_in[3];
    const float* W2        = (const float*)d_in[4];
    const float* b2        = (const float*)d_in[5];
    const float* raw_alpha = (const float*)d_in[6];
    const int*   e2g       = (const int*)d_in[7];
    int T = in_sizes[7];

    constexpr int SMEM_GEMM = (128 * 40 + 32 * 136) * 2 * 3;   // 56832 B
    cudaFuncSetAttribute(gemm_kernel<DDIM, false>,
                         cudaFuncAttributeMaxDynamicSharedMemorySize, SMEM_GEMM);
    cudaFuncSetAttribute(gemm_kernel<HDIM, true>,
                         cudaFuncAttributeMaxDynamicSharedMemorySize, SMEM_GEMM);

    prep_kernel<<<1, 256>>>(ids, e2g, raw_alpha, T);

    // streaming converts: NE*DDIM*HDIM / (256*8) = 3456 blocks
    convert_kernel<<<3456, 256>>>(W1, 0);
    convert_kernel<<<3456, 256>>>(W2, 1);

    gather_kernel<<<3072, 256>>>(x);

    gemm_kernel<DDIM, false><<<dim3(NTOK / 128, HDIM / 128, NE), 256, SMEM_GEMM>>>(b1, x);
    gemm_kernel<HDIM, true ><<<dim3(NTOK / 128, DDIM / 128, NE), 256, SMEM_GEMM>>>(b2, x);

    normalize_kernel<<<NTOK, 192>>>((float*)d_out);
}